// round 14
// baseline (speedup 1.0000x reference)
#include <cuda_runtime.h>
#include <cuda_fp16.h>
#include <math.h>
#include <stdint.h>

// Problem dims (fixed)
#define B_    16384
#define IN_   512
#define HID_  1024
#define OUT_  512
#define KC_   (IN_ + HID_)    // 1536
#define N4H   (4 * HID_)      // 4096

#define BM 128
#define BN 128
#define BSTR 136                 // B smem row stride (halves)

// gates: BK=48, 3 stages -> per-CTA smem = 3*(128*56 + 48*136)*2 = 82176 B
// fc:    BK=32, 3 stages -> per-CTA smem = 3*(128*40 + 32*136)*2 = 56832 B
#define SMEM_G ((3 * BM * 56 + 3 * 48 * BSTR) * 2)
#define SMEM_F ((3 * BM * 40 + 3 * 32 * BSTR) * 2)

// ---------------------------------------------------------------------------
// Static device scratch
// ---------------------------------------------------------------------------
__device__ __half g_X[(size_t)B_ * KC_];       // [B][x|h] fp16
__device__ __half g_W[(size_t)KC_ * N4H];      // [K][4H] concat [i|f|o|c], fp16
__device__ __half g_FT[(size_t)HID_ * OUT_];   // fc_w^T [HID][OUT], fp16
__device__ __half g_H[(size_t)B_ * HID_];      // h_new fp16
__device__ float g_bias[N4H];
__device__ float g_gates[(size_t)B_ * N4H];

// ---------------------------------------------------------------------------
// Helpers
// ---------------------------------------------------------------------------
__device__ __forceinline__ void store4h(__half* p, float4 v)
{
    union { __half b[4]; uint2 u; } H;
    H.b[0] = __float2half_rn(v.x);
    H.b[1] = __float2half_rn(v.y);
    H.b[2] = __float2half_rn(v.z);
    H.b[3] = __float2half_rn(v.w);
    *(uint2*)p = H.u;
}

__device__ __forceinline__ void cp16(void* sdst, const void* gsrc)
{
    uint32_t s = (uint32_t)__cvta_generic_to_shared(sdst);
    asm volatile("cp.async.cg.shared.global [%0], [%1], 16;" :: "r"(s), "l"(gsrc));
}
__device__ __forceinline__ void cp_commit() { asm volatile("cp.async.commit_group;"); }
__device__ __forceinline__ void cp_wait0()  { asm volatile("cp.async.wait_group 0;"); }
__device__ __forceinline__ void cp_wait1()  { asm volatile("cp.async.wait_group 1;"); }

__device__ __forceinline__ void ldm_x4(uint32_t* r, const __half* p)
{
    uint32_t a = (uint32_t)__cvta_generic_to_shared(p);
    asm volatile("ldmatrix.sync.aligned.m8n8.x4.shared.b16 {%0,%1,%2,%3}, [%4];"
                 : "=r"(r[0]), "=r"(r[1]), "=r"(r[2]), "=r"(r[3]) : "r"(a));
}
__device__ __forceinline__ void ldm_x4t(uint32_t* r, const __half* p)
{
    uint32_t a = (uint32_t)__cvta_generic_to_shared(p);
    asm volatile("ldmatrix.sync.aligned.m8n8.x4.trans.shared.b16 {%0,%1,%2,%3}, [%4];"
                 : "=r"(r[0]), "=r"(r[1]), "=r"(r[2]), "=r"(r[3]) : "r"(a));
}
__device__ __forceinline__ void mma_f16(float* c, const uint32_t* a, const uint32_t* b)
{
    asm volatile(
        "mma.sync.aligned.m16n8k16.row.col.f32.f16.f16.f32 "
        "{%0,%1,%2,%3}, {%4,%5,%6,%7}, {%8,%9}, {%0,%1,%2,%3};"
        : "+f"(c[0]), "+f"(c[1]), "+f"(c[2]), "+f"(c[3])
        : "r"(a[0]), "r"(a[1]), "r"(a[2]), "r"(a[3]), "r"(b[0]), "r"(b[1]));
}

// ---------------------------------------------------------------------------
// Conversion kernels
// ---------------------------------------------------------------------------
__global__ __launch_bounds__(256)
void conv_x_kernel(const float* __restrict__ x, const float* __restrict__ h)
{
    size_t t = (size_t)blockIdx.x * 256 + threadIdx.x;
    size_t m = t / (KC_ / 4);
    int c4 = (int)(t % (KC_ / 4)) * 4;
    float4 v = (c4 < IN_) ? *(const float4*)&x[m * IN_ + c4]
                          : *(const float4*)&h[m * HID_ + (c4 - IN_)];
    store4h(g_X + m * KC_ + c4, v);
}

__global__ __launch_bounds__(256)
void conv_w_kernel(const float* __restrict__ Wi, const float* __restrict__ Wf,
                   const float* __restrict__ Wo, const float* __restrict__ Wc,
                   const float* __restrict__ Ui, const float* __restrict__ Uf,
                   const float* __restrict__ Uo, const float* __restrict__ Uc)
{
    size_t t = (size_t)blockIdx.x * 256 + threadIdx.x;
    int k  = (int)(t / (N4H / 4));
    int c4 = (int)(t % (N4H / 4)) * 4;
    int g  = c4 >> 10;
    int j  = c4 & 1023;
    const float* W = (g == 0) ? Wi : (g == 1) ? Wf : (g == 2) ? Wo : Wc;
    const float* U = (g == 0) ? Ui : (g == 1) ? Uf : (g == 2) ? Uo : Uc;
    float4 v = (k < IN_) ? *(const float4*)&W[(size_t)k * HID_ + j]
                         : *(const float4*)&U[(size_t)(k - IN_) * HID_ + j];
    store4h(g_W + (size_t)k * N4H + c4, v);
}

__global__ __launch_bounds__(256)
void conv_fcw_kernel(const float* __restrict__ fcw)   // [OUT,HID] -> [HID,OUT] fp16
{
    size_t t = (size_t)blockIdx.x * 256 + threadIdx.x;
    int k  = (int)(t / (OUT_ / 4));
    int n4 = (int)(t % (OUT_ / 4)) * 4;
    float4 v;
    v.x = fcw[(size_t)(n4 + 0) * HID_ + k];
    v.y = fcw[(size_t)(n4 + 1) * HID_ + k];
    v.z = fcw[(size_t)(n4 + 2) * HID_ + k];
    v.w = fcw[(size_t)(n4 + 3) * HID_ + k];
    store4h(g_FT + (size_t)k * OUT_ + n4, v);
}

__global__ __launch_bounds__(256)
void conv_bias_kernel(const float* __restrict__ bi, const float* __restrict__ bf,
                      const float* __restrict__ bo, const float* __restrict__ bc)
{
    int n = blockIdx.x * 256 + threadIdx.x;
    int g = n >> 10, j = n & 1023;
    const float* b = (g == 0) ? bi : (g == 1) ? bf : (g == 2) ? bo : bc;
    g_bias[n] = b[j];
}

// ---------------------------------------------------------------------------
// fp16 GEMM, 3-stage cp.async pipeline (wait_group 1 keeps newest load in
// flight during compute). Templated on BK. A: [M,K]; B: [K,N]; both fp16.
// ---------------------------------------------------------------------------
template<int BKT>
__global__ __launch_bounds__(256)
void f16_gemm_kernel(const __half* __restrict__ Am, int lda,
                     const __half* __restrict__ Bm, int ldb,
                     const float* __restrict__ bias, float* __restrict__ C, int ldc, int K)
{
    constexpr int ASTRT = BKT + 8;          // A row stride (halves), mult of 8
    constexpr int KSN   = BKT / 16;         // ks sub-steps per stage
    constexpr int NCHK  = BKT / 16;         // 16B chunks per thread (A and B each)

    extern __shared__ __half sm[];
    __half* sA = sm;                        // 3 stages * BM*ASTRT
    __half* sB = sA + 3 * BM * ASTRT;       // 3 stages * BKT*BSTR

    const int tid  = threadIdx.x;
    const int m0   = blockIdx.y * BM;
    const int n0   = blockIdx.x * BN;
    const int warp = tid >> 5, lane = tid & 31;
    const int wm = (warp >> 2) * 64;
    const int wn = (warp & 3) * 32;

    float acc[4][4][4];
    #pragma unroll
    for (int mi = 0; mi < 4; mi++)
        #pragma unroll
        for (int ni = 0; ni < 4; ni++)
            #pragma unroll
            for (int q = 0; q < 4; q++) acc[mi][ni][q] = 0.0f;

    auto load_stage = [&](int s, int k0) {
        #pragma unroll
        for (int i = 0; i < NCHK; i++) {            // A: BM rows x BKT/8 chunks
            int c = tid + i * 256;
            int row = c / (BKT / 8), q = (c % (BKT / 8)) * 8;
            cp16(sA + s * BM * ASTRT + row * ASTRT + q,
                 Am + (size_t)(m0 + row) * lda + k0 + q);
        }
        #pragma unroll
        for (int i = 0; i < NCHK; i++) {            // B: BKT rows x 16 chunks
            int c = tid + i * 256;
            int row = c >> 4, q = (c & 15) * 8;
            cp16(sB + s * BKT * BSTR + row * BSTR + q,
                 Bm + (size_t)(k0 + row) * ldb + n0 + q);
        }
    };

    const int KT = K / BKT;
    load_stage(0, 0);
    cp_commit();
    load_stage(1, BKT);
    cp_commit();

    const int arow = lane & 15;
    const int asub = (lane >> 4) * 8;
    const int brow = (lane & 7) + ((lane >> 3) & 1) * 8;
    const int bsub = (lane >> 4) * 8;

    int s = 0, sl = 2;
    for (int kt = 0; kt < KT; kt++) {
        if (kt + 1 < KT) cp_wait1(); else cp_wait0();
        __syncthreads();
        if (kt + 2 < KT) { load_stage(sl, (kt + 2) * BKT); cp_commit(); }

        const __half* pA = sA + s * BM * ASTRT;
        const __half* pB = sB + s * BKT * BSTR;

        #pragma unroll
        for (int ks = 0; ks < KSN; ks++) {
            uint32_t aF[4][4], bF[4][2];
            const int ak = ks * 16 + asub;
            #pragma unroll
            for (int mi = 0; mi < 4; mi++)
                ldm_x4(aF[mi], pA + (wm + mi * 16 + arow) * ASTRT + ak);
            const int bk = ks * 16 + brow;
            #pragma unroll
            for (int nb = 0; nb < 2; nb++) {
                uint32_t r[4];
                ldm_x4t(r, pB + bk * BSTR + wn + nb * 16 + bsub);
                bF[nb * 2 + 0][0] = r[0]; bF[nb * 2 + 0][1] = r[1];
                bF[nb * 2 + 1][0] = r[2]; bF[nb * 2 + 1][1] = r[3];
            }
            #pragma unroll
            for (int mi = 0; mi < 4; mi++)
                #pragma unroll
                for (int ni = 0; ni < 4; ni++)
                    mma_f16(acc[mi][ni], aF[mi], bF[ni]);
        }

        s  = (s  == 2) ? 0 : s + 1;
        sl = (sl == 2) ? 0 : sl + 1;
    }

    // Epilogue: + bias, fp32 stores
    const int grow = lane >> 2;
    const int gcol = (lane & 3) * 2;
    #pragma unroll
    for (int mi = 0; mi < 4; mi++) {
        #pragma unroll
        for (int ni = 0; ni < 4; ni++) {
            int n = n0 + wn + ni * 8 + gcol;
            float b0 = bias[n], b1 = bias[n + 1];
            int r0 = m0 + wm + mi * 16 + grow;
            float2 v0 = {acc[mi][ni][0] + b0, acc[mi][ni][1] + b1};
            float2 v1 = {acc[mi][ni][2] + b0, acc[mi][ni][3] + b1};
            *(float2*)&C[(size_t)r0 * ldc + n] = v0;
            *(float2*)&C[(size_t)(r0 + 8) * ldc + n] = v1;
        }
    }
}

// ---------------------------------------------------------------------------
// Pointwise LSTM cell update (+ emit fp16 h_new for the fc GEMM)
// ---------------------------------------------------------------------------
__device__ __forceinline__ float sigmoidf_(float v) { return 1.0f / (1.0f + __expf(-v)); }

__global__ __launch_bounds__(256)
void pointwise_kernel(const float* __restrict__ c_t,
                      float* __restrict__ h_new, float* __restrict__ c_new)
{
    size_t idx = (size_t)blockIdx.x * 256 + threadIdx.x;
    size_t b = idx >> 8;
    size_t q = (idx & 255) * 4;

    const float* gp = &g_gates[b * (size_t)N4H + q];
    float4 gi = *(const float4*)(gp + 0 * HID_);
    float4 gf = *(const float4*)(gp + 1 * HID_);
    float4 go = *(const float4*)(gp + 2 * HID_);
    float4 gc = *(const float4*)(gp + 3 * HID_);
    float4 c  = *(const float4*)&c_t[b * HID_ + q];

    float4 cn, hn;
    cn.x = sigmoidf_(gf.x) * c.x + sigmoidf_(gi.x) * tanhf(gc.x);
    cn.y = sigmoidf_(gf.y) * c.y + sigmoidf_(gi.y) * tanhf(gc.y);
    cn.z = sigmoidf_(gf.z) * c.z + sigmoidf_(gi.z) * tanhf(gc.z);
    cn.w = sigmoidf_(gf.w) * c.w + sigmoidf_(gi.w) * tanhf(gc.w);
    hn.x = sigmoidf_(go.x) * tanhf(cn.x);
    hn.y = sigmoidf_(go.y) * tanhf(cn.y);
    hn.z = sigmoidf_(go.z) * tanhf(cn.z);
    hn.w = sigmoidf_(go.w) * tanhf(cn.w);

    *(float4*)&c_new[b * HID_ + q] = cn;
    *(float4*)&h_new[b * HID_ + q] = hn;
    store4h(g_H + b * HID_ + q, hn);
}

// ---------------------------------------------------------------------------
// Launch (gates GEMM is the 4th launch — profiled slot)
// ---------------------------------------------------------------------------
extern "C" void kernel_launch(void* const* d_in, const int* in_sizes, int n_in,
                              void* d_out, int out_size)
{
    const float* x   = (const float*)d_in[0];
    const float* h   = (const float*)d_in[1];
    const float* c   = (const float*)d_in[2];
    const float* Wi  = (const float*)d_in[3];
    const float* Ui  = (const float*)d_in[4];
    const float* bi  = (const float*)d_in[5];
    const float* Wf  = (const float*)d_in[6];
    const float* Uf  = (const float*)d_in[7];
    const float* bf  = (const float*)d_in[8];
    const float* Wo  = (const float*)d_in[9];
    const float* Uo  = (const float*)d_in[10];
    const float* bo  = (const float*)d_in[11];
    const float* Wc  = (const float*)d_in[12];
    const float* Uc  = (const float*)d_in[13];
    const float* bc  = (const float*)d_in[14];
    const float* fcw = (const float*)d_in[15];
    const float* fcb = (const float*)d_in[16];

    float* out   = (float*)d_out;
    float* h_new = out + (size_t)B_ * OUT_;
    float* c_new = h_new + (size_t)B_ * HID_;

    static int smem_set = 0;
    if (!smem_set) {
        cudaFuncSetAttribute(f16_gemm_kernel<48>,
                             cudaFuncAttributeMaxDynamicSharedMemorySize, SMEM_G);
        cudaFuncSetAttribute(f16_gemm_kernel<32>,
                             cudaFuncAttributeMaxDynamicSharedMemorySize, SMEM_F);
        smem_set = 1;
    }

    void *pX, *pW, *pFT, *pH, *pBias, *pGates;
    cudaGetSymbolAddress(&pX, g_X);
    cudaGetSymbolAddress(&pW, g_W);     cudaGetSymbolAddress(&pFT, g_FT);
    cudaGetSymbolAddress(&pH, g_H);
    cudaGetSymbolAddress(&pBias, g_bias); cudaGetSymbolAddress(&pGates, g_gates);

    // 1-3: conversions needed by the gates GEMM
    conv_x_kernel<<<(B_ * KC_ / 4) / 256, 256>>>(x, h);
    conv_w_kernel<<<(KC_ * N4H / 4) / 256, 256>>>(Wi, Wf, Wo, Wc, Ui, Uf, Uo, Uc);
    conv_bias_kernel<<<N4H / 256, 256>>>(bi, bf, bo, bc);

    // 4: gates GEMM (profiled slot): BK=48, 3 stages, KT=32
    dim3 g1(N4H / BN, B_ / BM);   // (32, 128)
    f16_gemm_kernel<48><<<g1, 256, SMEM_G>>>(
        (const __half*)pX, KC_,
        (const __half*)pW, N4H,
        (const float*)pBias, (float*)pGates, N4H, KC_);

    // 5: pointwise cell update
    pointwise_kernel<<<(B_ * HID_ / 4) / 256, 256>>>(c, h_new, c_new);

    // 6: fc weight conversion
    conv_fcw_kernel<<<(HID_ * OUT_ / 4) / 256, 256>>>(fcw);

    // 7: fc GEMM: BK=32, 3 stages, KT=32
    dim3 g2(OUT_ / BN, B_ / BM);  // (4, 128)
    f16_gemm_kernel<32><<<g2, 256, SMEM_F>>>(
        (const __half*)pH, HID_,
        (const __half*)pFT, OUT_,
        fcb, out, OUT_, HID_);
}

// round 15
// speedup vs baseline: 1.0329x; 1.0329x over previous
#include <cuda_runtime.h>
#include <cuda_fp16.h>
#include <math.h>
#include <stdint.h>

// Problem dims (fixed)
#define B_    16384
#define IN_   512
#define HID_  1024
#define OUT_  512
#define KC_   (IN_ + HID_)    // 1536
#define N4H   (4 * HID_)      // 4096

// GEMM tiling
#define BM 128
#define BN 128
#define BK 64
#define NSTAGE 3
#define ASTR 72     // A smem row stride in halves (64 + 8 pad)
#define BSTR 136    // B smem row stride in halves (128 + 8 pad)

// smem: 3 stages x (A + B) = 3*(128*72 + 64*136) halves = 107520 B
#define SMEM_GEMM ((NSTAGE * BM * ASTR + NSTAGE * BK * BSTR) * 2)

// ---------------------------------------------------------------------------
// Static device scratch
// ---------------------------------------------------------------------------
__device__ __half g_X[(size_t)B_ * KC_];       // [B][x|h] fp16
__device__ __half g_W[(size_t)KC_ * N4H];      // [K][4H] concat [i|f|o|c], fp16
__device__ __half g_FT[(size_t)HID_ * OUT_];   // fc_w^T [HID][OUT], fp16
__device__ __half g_H[(size_t)B_ * HID_];      // h_new fp16
__device__ float g_bias[N4H];
__device__ float g_gates[(size_t)B_ * N4H];

// ---------------------------------------------------------------------------
// Helpers
// ---------------------------------------------------------------------------
__device__ __forceinline__ void store4h(__half* p, float4 v)
{
    union { __half b[4]; uint2 u; } H;
    H.b[0] = __float2half_rn(v.x);
    H.b[1] = __float2half_rn(v.y);
    H.b[2] = __float2half_rn(v.z);
    H.b[3] = __float2half_rn(v.w);
    *(uint2*)p = H.u;
}

__device__ __forceinline__ void cp16(void* sdst, const void* gsrc)
{
    uint32_t s = (uint32_t)__cvta_generic_to_shared(sdst);
    asm volatile("cp.async.cg.shared.global [%0], [%1], 16;" :: "r"(s), "l"(gsrc));
}
__device__ __forceinline__ void cp_commit() { asm volatile("cp.async.commit_group;"); }
__device__ __forceinline__ void cp_wait0()  { asm volatile("cp.async.wait_group 0;"); }
__device__ __forceinline__ void cp_wait1()  { asm volatile("cp.async.wait_group 1;"); }

__device__ __forceinline__ void ldm_x4(uint32_t* r, const __half* p)
{
    uint32_t a = (uint32_t)__cvta_generic_to_shared(p);
    asm volatile("ldmatrix.sync.aligned.m8n8.x4.shared.b16 {%0,%1,%2,%3}, [%4];"
                 : "=r"(r[0]), "=r"(r[1]), "=r"(r[2]), "=r"(r[3]) : "r"(a));
}
__device__ __forceinline__ void ldm_x4t(uint32_t* r, const __half* p)
{
    uint32_t a = (uint32_t)__cvta_generic_to_shared(p);
    asm volatile("ldmatrix.sync.aligned.m8n8.x4.trans.shared.b16 {%0,%1,%2,%3}, [%4];"
                 : "=r"(r[0]), "=r"(r[1]), "=r"(r[2]), "=r"(r[3]) : "r"(a));
}
__device__ __forceinline__ void mma_f16(float* c, const uint32_t* a, const uint32_t* b)
{
    asm volatile(
        "mma.sync.aligned.m16n8k16.row.col.f32.f16.f16.f32 "
        "{%0,%1,%2,%3}, {%4,%5,%6,%7}, {%8,%9}, {%0,%1,%2,%3};"
        : "+f"(c[0]), "+f"(c[1]), "+f"(c[2]), "+f"(c[3])
        : "r"(a[0]), "r"(a[1]), "r"(a[2]), "r"(a[3]), "r"(b[0]), "r"(b[1]));
}

// ---------------------------------------------------------------------------
// Conversion kernels
// ---------------------------------------------------------------------------
__global__ __launch_bounds__(256)
void conv_x_kernel(const float* __restrict__ x, const float* __restrict__ h)
{
    size_t t = (size_t)blockIdx.x * 256 + threadIdx.x;
    size_t m = t / (KC_ / 4);
    int c4 = (int)(t % (KC_ / 4)) * 4;
    float4 v = (c4 < IN_) ? *(const float4*)&x[m * IN_ + c4]
                          : *(const float4*)&h[m * HID_ + (c4 - IN_)];
    store4h(g_X + m * KC_ + c4, v);
}

__global__ __launch_bounds__(256)
void conv_w_kernel(const float* __restrict__ Wi, const float* __restrict__ Wf,
                   const float* __restrict__ Wo, const float* __restrict__ Wc,
                   const float* __restrict__ Ui, const float* __restrict__ Uf,
                   const float* __restrict__ Uo, const float* __restrict__ Uc)
{
    size_t t = (size_t)blockIdx.x * 256 + threadIdx.x;
    int k  = (int)(t / (N4H / 4));
    int c4 = (int)(t % (N4H / 4)) * 4;
    int g  = c4 >> 10;
    int j  = c4 & 1023;
    const float* W = (g == 0) ? Wi : (g == 1) ? Wf : (g == 2) ? Wo : Wc;
    const float* U = (g == 0) ? Ui : (g == 1) ? Uf : (g == 2) ? Uo : Uc;
    float4 v = (k < IN_) ? *(const float4*)&W[(size_t)k * HID_ + j]
                         : *(const float4*)&U[(size_t)(k - IN_) * HID_ + j];
    store4h(g_W + (size_t)k * N4H + c4, v);
}

__global__ __launch_bounds__(256)
void conv_fcw_kernel(const float* __restrict__ fcw)   // [OUT,HID] -> [HID,OUT] fp16
{
    size_t t = (size_t)blockIdx.x * 256 + threadIdx.x;
    int k  = (int)(t / (OUT_ / 4));
    int n4 = (int)(t % (OUT_ / 4)) * 4;
    float4 v;
    v.x = fcw[(size_t)(n4 + 0) * HID_ + k];
    v.y = fcw[(size_t)(n4 + 1) * HID_ + k];
    v.z = fcw[(size_t)(n4 + 2) * HID_ + k];
    v.w = fcw[(size_t)(n4 + 3) * HID_ + k];
    store4h(g_FT + (size_t)k * OUT_ + n4, v);
}

__global__ __launch_bounds__(256)
void conv_bias_kernel(const float* __restrict__ bi, const float* __restrict__ bf,
                      const float* __restrict__ bo, const float* __restrict__ bc)
{
    int n = blockIdx.x * 256 + threadIdx.x;
    int g = n >> 10, j = n & 1023;
    const float* b = (g == 0) ? bi : (g == 1) ? bf : (g == 2) ? bo : bc;
    g_bias[n] = b[j];
}

// ---------------------------------------------------------------------------
// fp16 GEMM: C = A @ B (+bias). BK=64, 3-stage cp.async pipeline
// (wait_group 1 keeps the newest prefetch in flight during compute).
// ---------------------------------------------------------------------------
__global__ __launch_bounds__(256)
void f16_gemm_kernel(const __half* __restrict__ Am, int lda,
                     const __half* __restrict__ Bm, int ldb,
                     const float* __restrict__ bias, float* __restrict__ C, int ldc, int K)
{
    extern __shared__ __half sm[];
    __half* sA = sm;                        // NSTAGE * BM*ASTR
    __half* sB = sA + NSTAGE * BM * ASTR;   // NSTAGE * BK*BSTR

    const int tid  = threadIdx.x;
    const int m0   = blockIdx.y * BM;
    const int n0   = blockIdx.x * BN;
    const int warp = tid >> 5, lane = tid & 31;
    const int wm = (warp >> 2) * 64;
    const int wn = (warp & 3) * 32;

    float acc[4][4][4];
    #pragma unroll
    for (int mi = 0; mi < 4; mi++)
        #pragma unroll
        for (int ni = 0; ni < 4; ni++)
            #pragma unroll
            for (int q = 0; q < 4; q++) acc[mi][ni][q] = 0.0f;

    auto load_stage = [&](int s, int k0) {
        #pragma unroll
        for (int i = 0; i < 4; i++) {              // A: 128 rows x 8 chunks of 16B
            int c = tid + i * 256;
            int row = c >> 3, q = (c & 7) * 8;
            cp16(sA + s * BM * ASTR + row * ASTR + q,
                 Am + (size_t)(m0 + row) * lda + k0 + q);
        }
        #pragma unroll
        for (int i = 0; i < 4; i++) {              // B: 64 rows x 16 chunks of 16B
            int c = tid + i * 256;
            int row = c >> 4, q = (c & 15) * 8;
            cp16(sB + s * BK * BSTR + row * BSTR + q,
                 Bm + (size_t)(k0 + row) * ldb + n0 + q);
        }
    };

    const int KT = K / BK;
    load_stage(0, 0);
    cp_commit();
    load_stage(1, BK);
    cp_commit();

    const int arow = lane & 15;
    const int asub = (lane >> 4) * 8;
    const int brow = (lane & 7) + ((lane >> 3) & 1) * 8;
    const int bsub = (lane >> 4) * 8;

    int s = 0, sl = 2;
    for (int kt = 0; kt < KT; kt++) {
        if (kt + 1 < KT) cp_wait1(); else cp_wait0();
        __syncthreads();
        if (kt + 2 < KT) { load_stage(sl, (kt + 2) * BK); cp_commit(); }

        const __half* pA = sA + s * BM * ASTR;
        const __half* pB = sB + s * BK * BSTR;

        #pragma unroll
        for (int ks = 0; ks < 4; ks++) {
            uint32_t aF[4][4], bF[4][2];
            const int ak = ks * 16 + asub;
            #pragma unroll
            for (int mi = 0; mi < 4; mi++)
                ldm_x4(aF[mi], pA + (wm + mi * 16 + arow) * ASTR + ak);
            const int bk = ks * 16 + brow;
            #pragma unroll
            for (int nb = 0; nb < 2; nb++) {
                uint32_t r[4];
                ldm_x4t(r, pB + bk * BSTR + wn + nb * 16 + bsub);
                bF[nb * 2 + 0][0] = r[0]; bF[nb * 2 + 0][1] = r[1];
                bF[nb * 2 + 1][0] = r[2]; bF[nb * 2 + 1][1] = r[3];
            }
            #pragma unroll
            for (int mi = 0; mi < 4; mi++)
                #pragma unroll
                for (int ni = 0; ni < 4; ni++)
                    mma_f16(acc[mi][ni], aF[mi], bF[ni]);
        }

        s  = (s  == NSTAGE - 1) ? 0 : s + 1;
        sl = (sl == NSTAGE - 1) ? 0 : sl + 1;
    }

    // Epilogue: + bias, fp32 stores
    const int grow = lane >> 2;
    const int gcol = (lane & 3) * 2;
    #pragma unroll
    for (int mi = 0; mi < 4; mi++) {
        #pragma unroll
        for (int ni = 0; ni < 4; ni++) {
            int n = n0 + wn + ni * 8 + gcol;
            float b0 = bias[n], b1 = bias[n + 1];
            int r0 = m0 + wm + mi * 16 + grow;
            float2 v0 = {acc[mi][ni][0] + b0, acc[mi][ni][1] + b1};
            float2 v1 = {acc[mi][ni][2] + b0, acc[mi][ni][3] + b1};
            *(float2*)&C[(size_t)r0 * ldc + n] = v0;
            *(float2*)&C[(size_t)(r0 + 8) * ldc + n] = v1;
        }
    }
}

// ---------------------------------------------------------------------------
// Pointwise LSTM cell update (+ emit fp16 h_new for the fc GEMM)
// ---------------------------------------------------------------------------
__device__ __forceinline__ float sigmoidf_(float v) { return 1.0f / (1.0f + __expf(-v)); }

__global__ __launch_bounds__(256)
void pointwise_kernel(const float* __restrict__ c_t,
                      float* __restrict__ h_new, float* __restrict__ c_new)
{
    size_t idx = (size_t)blockIdx.x * 256 + threadIdx.x;
    size_t b = idx >> 8;
    size_t q = (idx & 255) * 4;

    const float* gp = &g_gates[b * (size_t)N4H + q];
    float4 gi = *(const float4*)(gp + 0 * HID_);
    float4 gf = *(const float4*)(gp + 1 * HID_);
    float4 go = *(const float4*)(gp + 2 * HID_);
    float4 gc = *(const float4*)(gp + 3 * HID_);
    float4 c  = *(const float4*)&c_t[b * HID_ + q];

    float4 cn, hn;
    cn.x = sigmoidf_(gf.x) * c.x + sigmoidf_(gi.x) * tanhf(gc.x);
    cn.y = sigmoidf_(gf.y) * c.y + sigmoidf_(gi.y) * tanhf(gc.y);
    cn.z = sigmoidf_(gf.z) * c.z + sigmoidf_(gi.z) * tanhf(gc.z);
    cn.w = sigmoidf_(gf.w) * c.w + sigmoidf_(gi.w) * tanhf(gc.w);
    hn.x = sigmoidf_(go.x) * tanhf(cn.x);
    hn.y = sigmoidf_(go.y) * tanhf(cn.y);
    hn.z = sigmoidf_(go.z) * tanhf(cn.z);
    hn.w = sigmoidf_(go.w) * tanhf(cn.w);

    *(float4*)&c_new[b * HID_ + q] = cn;
    *(float4*)&h_new[b * HID_ + q] = hn;
    store4h(g_H + b * HID_ + q, hn);
}

// ---------------------------------------------------------------------------
// Launch (gates GEMM is the 4th launch — profiled slot)
// ---------------------------------------------------------------------------
extern "C" void kernel_launch(void* const* d_in, const int* in_sizes, int n_in,
                              void* d_out, int out_size)
{
    const float* x   = (const float*)d_in[0];
    const float* h   = (const float*)d_in[1];
    const float* c   = (const float*)d_in[2];
    const float* Wi  = (const float*)d_in[3];
    const float* Ui  = (const float*)d_in[4];
    const float* bi  = (const float*)d_in[5];
    const float* Wf  = (const float*)d_in[6];
    const float* Uf  = (const float*)d_in[7];
    const float* bf  = (const float*)d_in[8];
    const float* Wo  = (const float*)d_in[9];
    const float* Uo  = (const float*)d_in[10];
    const float* bo  = (const float*)d_in[11];
    const float* Wc  = (const float*)d_in[12];
    const float* Uc  = (const float*)d_in[13];
    const float* bc  = (const float*)d_in[14];
    const float* fcw = (const float*)d_in[15];
    const float* fcb = (const float*)d_in[16];

    float* out   = (float*)d_out;
    float* h_new = out + (size_t)B_ * OUT_;
    float* c_new = h_new + (size_t)B_ * HID_;

    static int smem_set = 0;
    if (!smem_set) {
        cudaFuncSetAttribute(f16_gemm_kernel,
                             cudaFuncAttributeMaxDynamicSharedMemorySize, SMEM_GEMM);
        smem_set = 1;
    }

    void *pX, *pW, *pFT, *pH, *pBias, *pGates;
    cudaGetSymbolAddress(&pX, g_X);
    cudaGetSymbolAddress(&pW, g_W);     cudaGetSymbolAddress(&pFT, g_FT);
    cudaGetSymbolAddress(&pH, g_H);
    cudaGetSymbolAddress(&pBias, g_bias); cudaGetSymbolAddress(&pGates, g_gates);

    // 1-3: conversions needed by the gates GEMM
    conv_x_kernel<<<(B_ * KC_ / 4) / 256, 256>>>(x, h);
    conv_w_kernel<<<(KC_ * N4H / 4) / 256, 256>>>(Wi, Wf, Wo, Wc, Ui, Uf, Uo, Uc);
    conv_bias_kernel<<<N4H / 256, 256>>>(bi, bf, bo, bc);

    // 4: gates GEMM (profiled slot): BK=64, 3 stages, KT=24
    dim3 g1(N4H / BN, B_ / BM);   // (32, 128)
    f16_gemm_kernel<<<g1, 256, SMEM_GEMM>>>(
        (const __half*)pX, KC_,
        (const __half*)pW, N4H,
        (const float*)pBias, (float*)pGates, N4H, KC_);

    // 5: pointwise cell update
    pointwise_kernel<<<(B_ * HID_ / 4) / 256, 256>>>(c, h_new, c_new);

    // 6: fc weight conversion
    conv_fcw_kernel<<<(HID_ * OUT_ / 4) / 256, 256>>>(fcw);

    // 7: fc GEMM: BK=64, 3 stages, KT=16
    dim3 g2(OUT_ / BN, B_ / BM);  // (4, 128)
    f16_gemm_kernel<<<g2, 256, SMEM_GEMM>>>(
        (const __half*)pH, HID_,
        (const __half*)pFT, OUT_,
        fcb, out, OUT_, HID_);
}

// round 16
// speedup vs baseline: 1.0844x; 1.0498x over previous
#include <cuda_runtime.h>
#include <cuda_fp16.h>
#include <math.h>
#include <stdint.h>

// Problem dims (fixed)
#define B_    16384
#define IN_   512
#define HID_  1024
#define OUT_  512
#define KC_   (IN_ + HID_)    // 1536
#define N4H   (4 * HID_)      // 4096

// GEMM tiling (R12-proven best: 2 stages, BK=64, 2 CTAs/SM)
#define BM 128
#define BN 128
#define BK 64
#define ASTR 72     // A smem row stride in halves (64 + 8 pad)
#define BSTR 136    // B smem row stride in halves (128 + 8 pad)

// smem: 2 stages x (A + B) = 2*(128*72 + 64*136) halves = 71680 B
#define SMEM_GEMM ((2 * BM * ASTR + 2 * BK * BSTR) * 2)

// ---------------------------------------------------------------------------
// Static device scratch
// ---------------------------------------------------------------------------
__device__ __half g_X[(size_t)B_ * KC_];       // [B][x|h] fp16
__device__ __half g_W[(size_t)KC_ * N4H];      // [K][4H] concat [i|f|o|c], fp16
__device__ __half g_FT[(size_t)HID_ * OUT_];   // fc_w^T [HID][OUT], fp16
__device__ __half g_H[(size_t)B_ * HID_];      // h_new fp16
__device__ float g_bias[N4H];
__device__ __half g_gates[(size_t)B_ * N4H];   // fp16 pre-activations

// ---------------------------------------------------------------------------
// Helpers
// ---------------------------------------------------------------------------
__device__ __forceinline__ void store4h(__half* p, float4 v)
{
    union { __half b[4]; uint2 u; } H;
    H.b[0] = __float2half_rn(v.x);
    H.b[1] = __float2half_rn(v.y);
    H.b[2] = __float2half_rn(v.z);
    H.b[3] = __float2half_rn(v.w);
    *(uint2*)p = H.u;
}

__device__ __forceinline__ void cp16(void* sdst, const void* gsrc)
{
    uint32_t s = (uint32_t)__cvta_generic_to_shared(sdst);
    asm volatile("cp.async.cg.shared.global [%0], [%1], 16;" :: "r"(s), "l"(gsrc));
}
__device__ __forceinline__ void cp_commit() { asm volatile("cp.async.commit_group;"); }
__device__ __forceinline__ void cp_wait0()  { asm volatile("cp.async.wait_group 0;"); }

__device__ __forceinline__ void ldm_x4(uint32_t* r, const __half* p)
{
    uint32_t a = (uint32_t)__cvta_generic_to_shared(p);
    asm volatile("ldmatrix.sync.aligned.m8n8.x4.shared.b16 {%0,%1,%2,%3}, [%4];"
                 : "=r"(r[0]), "=r"(r[1]), "=r"(r[2]), "=r"(r[3]) : "r"(a));
}
__device__ __forceinline__ void ldm_x4t(uint32_t* r, const __half* p)
{
    uint32_t a = (uint32_t)__cvta_generic_to_shared(p);
    asm volatile("ldmatrix.sync.aligned.m8n8.x4.trans.shared.b16 {%0,%1,%2,%3}, [%4];"
                 : "=r"(r[0]), "=r"(r[1]), "=r"(r[2]), "=r"(r[3]) : "r"(a));
}
__device__ __forceinline__ void mma_f16(float* c, const uint32_t* a, const uint32_t* b)
{
    asm volatile(
        "mma.sync.aligned.m16n8k16.row.col.f32.f16.f16.f32 "
        "{%0,%1,%2,%3}, {%4,%5,%6,%7}, {%8,%9}, {%0,%1,%2,%3};"
        : "+f"(c[0]), "+f"(c[1]), "+f"(c[2]), "+f"(c[3])
        : "r"(a[0]), "r"(a[1]), "r"(a[2]), "r"(a[3]), "r"(b[0]), "r"(b[1]));
}

// ---------------------------------------------------------------------------
// Conversion kernels
// ---------------------------------------------------------------------------
__global__ __launch_bounds__(256)
void conv_x_kernel(const float* __restrict__ x, const float* __restrict__ h)
{
    size_t t = (size_t)blockIdx.x * 256 + threadIdx.x;
    size_t m = t / (KC_ / 4);
    int c4 = (int)(t % (KC_ / 4)) * 4;
    float4 v = (c4 < IN_) ? *(const float4*)&x[m * IN_ + c4]
                          : *(const float4*)&h[m * HID_ + (c4 - IN_)];
    store4h(g_X + m * KC_ + c4, v);
}

__global__ __launch_bounds__(256)
void conv_w_kernel(const float* __restrict__ Wi, const float* __restrict__ Wf,
                   const float* __restrict__ Wo, const float* __restrict__ Wc,
                   const float* __restrict__ Ui, const float* __restrict__ Uf,
                   const float* __restrict__ Uo, const float* __restrict__ Uc)
{
    size_t t = (size_t)blockIdx.x * 256 + threadIdx.x;
    int k  = (int)(t / (N4H / 4));
    int c4 = (int)(t % (N4H / 4)) * 4;
    int g  = c4 >> 10;
    int j  = c4 & 1023;
    const float* W = (g == 0) ? Wi : (g == 1) ? Wf : (g == 2) ? Wo : Wc;
    const float* U = (g == 0) ? Ui : (g == 1) ? Uf : (g == 2) ? Uo : Uc;
    float4 v = (k < IN_) ? *(const float4*)&W[(size_t)k * HID_ + j]
                         : *(const float4*)&U[(size_t)(k - IN_) * HID_ + j];
    store4h(g_W + (size_t)k * N4H + c4, v);
}

__global__ __launch_bounds__(256)
void conv_fcw_kernel(const float* __restrict__ fcw)   // [OUT,HID] -> [HID,OUT] fp16
{
    size_t t = (size_t)blockIdx.x * 256 + threadIdx.x;
    int k  = (int)(t / (OUT_ / 4));
    int n4 = (int)(t % (OUT_ / 4)) * 4;
    float4 v;
    v.x = fcw[(size_t)(n4 + 0) * HID_ + k];
    v.y = fcw[(size_t)(n4 + 1) * HID_ + k];
    v.z = fcw[(size_t)(n4 + 2) * HID_ + k];
    v.w = fcw[(size_t)(n4 + 3) * HID_ + k];
    store4h(g_FT + (size_t)k * OUT_ + n4, v);
}

__global__ __launch_bounds__(256)
void conv_bias_kernel(const float* __restrict__ bi, const float* __restrict__ bf,
                      const float* __restrict__ bo, const float* __restrict__ bc)
{
    int n = blockIdx.x * 256 + threadIdx.x;
    int g = n >> 10, j = n & 1023;
    const float* b = (g == 0) ? bi : (g == 1) ? bf : (g == 2) ? bo : bc;
    g_bias[n] = b[j];
}

// ---------------------------------------------------------------------------
// fp16 GEMM: C = A @ B (+bias). A: [M,K] fp16; B: [K,N] fp16.
// 2-stage cp.async pipeline, BK=64 (proven best). Output templated:
// HALF_OUT=1 stores fp16 (gates), 0 stores fp32 (fc).
// ---------------------------------------------------------------------------
template<int HALF_OUT>
__global__ __launch_bounds__(256)
void f16_gemm_kernel(const __half* __restrict__ Am, int lda,
                     const __half* __restrict__ Bm, int ldb,
                     const float* __restrict__ bias, void* __restrict__ Cv,
                     int ldc, int K)
{
    extern __shared__ __half sm[];
    __half* sA = sm;                        // 2 stages * BM*ASTR
    __half* sB = sA + 2 * BM * ASTR;        // 2 stages * BK*BSTR

    const int tid  = threadIdx.x;
    const int m0   = blockIdx.y * BM;
    const int n0   = blockIdx.x * BN;
    const int warp = tid >> 5, lane = tid & 31;
    const int wm = (warp >> 2) * 64;
    const int wn = (warp & 3) * 32;

    float acc[4][4][4];
    #pragma unroll
    for (int mi = 0; mi < 4; mi++)
        #pragma unroll
        for (int ni = 0; ni < 4; ni++)
            #pragma unroll
            for (int q = 0; q < 4; q++) acc[mi][ni][q] = 0.0f;

    auto load_stage = [&](int s, int k0) {
        #pragma unroll
        for (int i = 0; i < 4; i++) {              // A: 128 rows x 8 chunks of 16B
            int c = tid + i * 256;
            int row = c >> 3, q = (c & 7) * 8;
            cp16(sA + s * BM * ASTR + row * ASTR + q,
                 Am + (size_t)(m0 + row) * lda + k0 + q);
        }
        #pragma unroll
        for (int i = 0; i < 4; i++) {              // B: 64 rows x 16 chunks of 16B
            int c = tid + i * 256;
            int row = c >> 4, q = (c & 15) * 8;
            cp16(sB + s * BK * BSTR + row * BSTR + q,
                 Bm + (size_t)(k0 + row) * ldb + n0 + q);
        }
    };

    load_stage(0, 0);
    cp_commit();

    const int KT = K / BK;
    const int arow = lane & 15;
    const int asub = (lane >> 4) * 8;
    const int brow = (lane & 7) + ((lane >> 3) & 1) * 8;
    const int bsub = (lane >> 4) * 8;

    for (int kt = 0; kt < KT; kt++) {
        int s = kt & 1;
        cp_wait0();
        __syncthreads();
        if (kt + 1 < KT) { load_stage(s ^ 1, (kt + 1) * BK); cp_commit(); }

        const __half* pA = sA + s * BM * ASTR;
        const __half* pB = sB + s * BK * BSTR;

        #pragma unroll
        for (int ks = 0; ks < 4; ks++) {
            uint32_t aF[4][4], bF[4][2];
            const int ak = ks * 16 + asub;
            #pragma unroll
            for (int mi = 0; mi < 4; mi++)
                ldm_x4(aF[mi], pA + (wm + mi * 16 + arow) * ASTR + ak);
            const int bk = ks * 16 + brow;
            #pragma unroll
            for (int nb = 0; nb < 2; nb++) {
                uint32_t r[4];
                ldm_x4t(r, pB + bk * BSTR + wn + nb * 16 + bsub);
                bF[nb * 2 + 0][0] = r[0]; bF[nb * 2 + 0][1] = r[1];
                bF[nb * 2 + 1][0] = r[2]; bF[nb * 2 + 1][1] = r[3];
            }
            #pragma unroll
            for (int mi = 0; mi < 4; mi++)
                #pragma unroll
                for (int ni = 0; ni < 4; ni++)
                    mma_f16(acc[mi][ni], aF[mi], bF[ni]);
        }
    }

    // Epilogue: + bias; store fp16 (gates) or fp32 (fc)
    const int grow = lane >> 2;
    const int gcol = (lane & 3) * 2;
    #pragma unroll
    for (int mi = 0; mi < 4; mi++) {
        #pragma unroll
        for (int ni = 0; ni < 4; ni++) {
            int n = n0 + wn + ni * 8 + gcol;
            float b0 = bias[n], b1 = bias[n + 1];
            int r0 = m0 + wm + mi * 16 + grow;
            float v00 = acc[mi][ni][0] + b0, v01 = acc[mi][ni][1] + b1;
            float v10 = acc[mi][ni][2] + b0, v11 = acc[mi][ni][3] + b1;
            if (HALF_OUT) {
                __half* C = (__half*)Cv;
                __half2 h0 = __floats2half2_rn(v00, v01);
                __half2 h1 = __floats2half2_rn(v10, v11);
                *(__half2*)&C[(size_t)r0 * ldc + n] = h0;
                *(__half2*)&C[(size_t)(r0 + 8) * ldc + n] = h1;
            } else {
                float* C = (float*)Cv;
                *(float2*)&C[(size_t)r0 * ldc + n] = make_float2(v00, v01);
                *(float2*)&C[(size_t)(r0 + 8) * ldc + n] = make_float2(v10, v11);
            }
        }
    }
}

// ---------------------------------------------------------------------------
// Pointwise LSTM cell update (reads fp16 gates; emits fp16 h_new too)
// ---------------------------------------------------------------------------
__device__ __forceinline__ float sigmoidf_(float v) { return 1.0f / (1.0f + __expf(-v)); }

__device__ __forceinline__ float4 load4h(const __half* p)
{
    uint2 u = *(const uint2*)p;
    __half2 a = *(__half2*)&u.x, b = *(__half2*)&u.y;
    float2 fa = __half22float2(a), fb = __half22float2(b);
    return make_float4(fa.x, fa.y, fb.x, fb.y);
}

__global__ __launch_bounds__(256)
void pointwise_kernel(const float* __restrict__ c_t,
                      float* __restrict__ h_new, float* __restrict__ c_new)
{
    size_t idx = (size_t)blockIdx.x * 256 + threadIdx.x;
    size_t b = idx >> 8;
    size_t q = (idx & 255) * 4;

    const __half* gp = &g_gates[b * (size_t)N4H + q];
    float4 gi = load4h(gp + 0 * HID_);
    float4 gf = load4h(gp + 1 * HID_);
    float4 go = load4h(gp + 2 * HID_);
    float4 gc = load4h(gp + 3 * HID_);
    float4 c  = *(const float4*)&c_t[b * HID_ + q];

    float4 cn, hn;
    cn.x = sigmoidf_(gf.x) * c.x + sigmoidf_(gi.x) * tanhf(gc.x);
    cn.y = sigmoidf_(gf.y) * c.y + sigmoidf_(gi.y) * tanhf(gc.y);
    cn.z = sigmoidf_(gf.z) * c.z + sigmoidf_(gi.z) * tanhf(gc.z);
    cn.w = sigmoidf_(gf.w) * c.w + sigmoidf_(gi.w) * tanhf(gc.w);
    hn.x = sigmoidf_(go.x) * tanhf(cn.x);
    hn.y = sigmoidf_(go.y) * tanhf(cn.y);
    hn.z = sigmoidf_(go.z) * tanhf(cn.z);
    hn.w = sigmoidf_(go.w) * tanhf(cn.w);

    *(float4*)&c_new[b * HID_ + q] = cn;
    *(float4*)&h_new[b * HID_ + q] = hn;
    store4h(g_H + b * HID_ + q, hn);
}

// ---------------------------------------------------------------------------
// Launch (gates GEMM is the 4th launch — profiled slot)
// ---------------------------------------------------------------------------
extern "C" void kernel_launch(void* const* d_in, const int* in_sizes, int n_in,
                              void* d_out, int out_size)
{
    const float* x   = (const float*)d_in[0];
    const float* h   = (const float*)d_in[1];
    const float* c   = (const float*)d_in[2];
    const float* Wi  = (const float*)d_in[3];
    const float* Ui  = (const float*)d_in[4];
    const float* bi  = (const float*)d_in[5];
    const float* Wf  = (const float*)d_in[6];
    const float* Uf  = (const float*)d_in[7];
    const float* bf  = (const float*)d_in[8];
    const float* Wo  = (const float*)d_in[9];
    const float* Uo  = (const float*)d_in[10];
    const float* bo  = (const float*)d_in[11];
    const float* Wc  = (const float*)d_in[12];
    const float* Uc  = (const float*)d_in[13];
    const float* bc  = (const float*)d_in[14];
    const float* fcw = (const float*)d_in[15];
    const float* fcb = (const float*)d_in[16];

    float* out   = (float*)d_out;
    float* h_new = out + (size_t)B_ * OUT_;
    float* c_new = h_new + (size_t)B_ * HID_;

    static int smem_set = 0;
    if (!smem_set) {
        cudaFuncSetAttribute(f16_gemm_kernel<1>,
                             cudaFuncAttributeMaxDynamicSharedMemorySize, SMEM_GEMM);
        cudaFuncSetAttribute(f16_gemm_kernel<0>,
                             cudaFuncAttributeMaxDynamicSharedMemorySize, SMEM_GEMM);
        smem_set = 1;
    }

    void *pX, *pW, *pFT, *pH, *pBias, *pGates;
    cudaGetSymbolAddress(&pX, g_X);
    cudaGetSymbolAddress(&pW, g_W);     cudaGetSymbolAddress(&pFT, g_FT);
    cudaGetSymbolAddress(&pH, g_H);
    cudaGetSymbolAddress(&pBias, g_bias); cudaGetSymbolAddress(&pGates, g_gates);

    // 1-3: conversions needed by the gates GEMM
    conv_x_kernel<<<(B_ * KC_ / 4) / 256, 256>>>(x, h);
    conv_w_kernel<<<(KC_ * N4H / 4) / 256, 256>>>(Wi, Wf, Wo, Wc, Ui, Uf, Uo, Uc);
    conv_bias_kernel<<<N4H / 256, 256>>>(bi, bf, bo, bc);

    // 4: gates GEMM (profiled slot): fp16 output
    dim3 g1(N4H / BN, B_ / BM);   // (32, 128)
    f16_gemm_kernel<1><<<g1, 256, SMEM_GEMM>>>(
        (const __half*)pX, KC_,
        (const __half*)pW, N4H,
        (const float*)pBias, pGates, N4H, KC_);

    // 5: pointwise cell update
    pointwise_kernel<<<(B_ * HID_ / 4) / 256, 256>>>(c, h_new, c_new);

    // 6: fc weight conversion
    conv_fcw_kernel<<<(HID_ * OUT_ / 4) / 256, 256>>>(fcw);

    // 7: fc GEMM: fp32 output
    dim3 g2(OUT_ / BN, B_ / BM);  // (4, 128)
    f16_gemm_kernel<0><<<g2, 256, SMEM_GEMM>>>(
        (const __half*)pH, HID_,
        (const __half*)pFT, OUT_,
        fcb, out, OUT_, HID_);
}